// round 3
// baseline (speedup 1.0000x reference)
#include <cuda_runtime.h>
#include <math.h>
#include <stdint.h>

// Problem constants
#define NB   4
#define CC   128
#define HH   128
#define WW   256
#define HWSZ (HH * WW)          // 32768
#define NHW  (NB * HWSZ)        // 131072
#define DIM  128
#define NWP  4
#define PAD  136                // smem row pitch (words); 136%32==8 -> conflict-free frags
#define QPIT 132                // Q/out staging pitch

// Device-global scratch
__device__ float g_K[(size_t)NHW * DIM];
__device__ float g_V[(size_t)NHW * DIM];
__device__ float g_kb[NWP * DIM];
__device__ float g_vb[NWP * DIM];

__device__ __forceinline__ float inv_dt(int t2) {
    return exp2f(-(float)t2 * (13.287712379549449f / 32.0f));
}

__device__ __forceinline__ uint32_t f2tf32(float x) {
    uint32_t u;
    asm("cvt.rna.tf32.f32 %0, %1;" : "=r"(u) : "f"(x));
    return u;
}

__device__ __forceinline__ void mma_tf32(float d[4], const uint32_t a[4],
                                         uint32_t b0, uint32_t b1) {
    asm volatile(
        "mma.sync.aligned.m16n8k8.row.col.f32.tf32.tf32.f32 "
        "{%0,%1,%2,%3}, {%4,%5,%6,%7}, {%8,%9}, {%0,%1,%2,%3};\n"
        : "+f"(d[0]), "+f"(d[1]), "+f"(d[2]), "+f"(d[3])
        : "r"(a[0]), "r"(a[1]), "r"(a[2]), "r"(a[3]), "r"(b0), "r"(b1));
}

// ---------------------------------------------------------------------------
// Kernel 0: window position-bias projections
// ---------------------------------------------------------------------------
__global__ void bias_kernel(const float* __restrict__ kw, const float* __restrict__ kb,
                            const float* __restrict__ vw, const float* __restrict__ vb) {
    __shared__ float pb[NWP * DIM];
    int t = threadIdx.x;                  // 0..511
    {
        int w  = t >> 7;
        int i  = t & 127;
        int oy = w >> 1, ox = w & 1;
        float coord = (i < 64) ? (float)oy : (float)ox;
        int ii = i & 63;
        int t2 = ii >> 1;
        float arg = coord * (6.283185307179586f / 1.000001f) * inv_dt(t2);
        float s, c;
        sincosf(arg, &s, &c);
        pb[t] = (ii & 1) ? c : s;
    }
    __syncthreads();
    int w = t >> 7, d = t & 127;
    float accK = 0.f, accV = 0.f;
    const float* pbr = pb + w * DIM;
#pragma unroll 8
    for (int c = 0; c < DIM; ++c) {
        float p = pbr[c];
        accK += p * kw[c * DIM + d];
        accV += p * vw[c * DIM + d];
    }
    g_kb[t] = accK + kb[d];
    g_vb[t] = accV + vb[d];
}

// ---------------------------------------------------------------------------
// Kernel 1: g_K = feat_supp @ k_w ; g_V = feat_supp @ v_w (tf32 mma.sync)
// tf32 conversion done ONCE at smem-fill time.
// ---------------------------------------------------------------------------
__global__ __launch_bounds__(512, 1)
void gemm_kv_kernel(const float* __restrict__ feat,
                    const float* __restrict__ kw,
                    const float* __restrict__ vw) {
    extern __shared__ float sm[];
    float* As = sm;
    float* Bk = sm + 128 * PAD;
    float* Bv = sm + 2 * 128 * PAD;
    int t  = threadIdx.x;
    int m0 = blockIdx.x * 128;
    int n    = m0 / HWSZ;
    int pix0 = m0 % HWSZ;

#pragma unroll 4
    for (int j = 0; j < 32; ++j) {
        int li = j * 512 + t;
        int c = li >> 7, m = li & 127;
        As[c * PAD + m] = __uint_as_float(f2tf32(feat[(size_t)(n * CC + c) * HWSZ + pix0 + m]));
    }
#pragma unroll 4
    for (int j = 0; j < 32; ++j) {
        int li = j * 512 + t;
        int c = li >> 7, d = li & 127;
        Bk[c * PAD + d] = __uint_as_float(f2tf32(kw[li]));
        Bv[c * PAD + d] = __uint_as_float(f2tf32(vw[li]));
    }
    __syncthreads();

    int w = t >> 5, lane = t & 31;
    int m0w = (w & 3) * 32, n0w = (w >> 2) * 32;
    int q = lane & 3, g = lane >> 2;

    float accK[2][4][4];
    float accV[2][4][4];
#pragma unroll
    for (int mi = 0; mi < 2; ++mi)
#pragma unroll
        for (int nj = 0; nj < 4; ++nj)
#pragma unroll
            for (int e = 0; e < 4; ++e) { accK[mi][nj][e] = 0.f; accV[mi][nj][e] = 0.f; }

#pragma unroll
    for (int kk = 0; kk < 16; ++kk) {
        int k0 = kk * 8;
        uint32_t a[2][4];
#pragma unroll
        for (int mi = 0; mi < 2; ++mi) {
            int m = m0w + mi * 16 + g;
            a[mi][0] = __float_as_uint(As[(k0 + q) * PAD + m]);
            a[mi][1] = __float_as_uint(As[(k0 + q) * PAD + m + 8]);
            a[mi][2] = __float_as_uint(As[(k0 + q + 4) * PAD + m]);
            a[mi][3] = __float_as_uint(As[(k0 + q + 4) * PAD + m + 8]);
        }
#pragma unroll
        for (int nj = 0; nj < 4; ++nj) {
            int nn = n0w + nj * 8 + g;
            uint32_t bk0 = __float_as_uint(Bk[(k0 + q) * PAD + nn]);
            uint32_t bk1 = __float_as_uint(Bk[(k0 + q + 4) * PAD + nn]);
            uint32_t bv0 = __float_as_uint(Bv[(k0 + q) * PAD + nn]);
            uint32_t bv1 = __float_as_uint(Bv[(k0 + q + 4) * PAD + nn]);
#pragma unroll
            for (int mi = 0; mi < 2; ++mi) {
                mma_tf32(accK[mi][nj], a[mi], bk0, bk1);
                mma_tf32(accV[mi][nj], a[mi], bv0, bv1);
            }
        }
    }

#pragma unroll
    for (int mi = 0; mi < 2; ++mi) {
#pragma unroll
        for (int nj = 0; nj < 4; ++nj) {
            int r0 = m0 + m0w + mi * 16 + g;
            int cb = n0w + nj * 8 + q * 2;
            *(float2*)(g_K + (size_t)r0 * DIM + cb) =
                make_float2(accK[mi][nj][0], accK[mi][nj][1]);
            *(float2*)(g_K + (size_t)(r0 + 8) * DIM + cb) =
                make_float2(accK[mi][nj][2], accK[mi][nj][3]);
            *(float2*)(g_V + (size_t)r0 * DIM + cb) =
                make_float2(accV[mi][nj][0], accV[mi][nj][1]);
            *(float2*)(g_V + (size_t)(r0 + 8) * DIM + cb) =
                make_float2(accV[mi][nj][2], accV[mi][nj][3]);
        }
    }
}

// ---------------------------------------------------------------------------
// Kernel 2: FUSED  Q-GEMM + attention.
// Stage A: As = feat_curr tile + PE(frac(flow)), Bs = q_w (tf32).
// Stage B: Q = As @ Bs (tf32 mma), Qs = (Q + qb) * scale  -> aliases As.
// Stage C: warp-per-pixel attention over gathered g_K/g_V; Os aliases Bs.
// Stage D: coalesced channel-major output writes.
// CTA = 128 contiguous pixels (never crosses an image row: W=256, tile=128).
// ---------------------------------------------------------------------------
__global__ __launch_bounds__(512, 1)
void q_attn_kernel(const float* __restrict__ feat,
                   const float* __restrict__ flow,
                   const float* __restrict__ qw,
                   const float* __restrict__ qb,
                   float* __restrict__ out) {
    extern __shared__ float sm[];
    float* As = sm;                 // [128 c][PAD m]  -> later Qs [128 m][QPIT d]
    float* Bs = sm + 128 * PAD;     // [128 c][PAD d]  -> later Os [128 m][QPIT d]
    __shared__ float s_kb[NWP * DIM];
    __shared__ float s_vb[NWP * DIM];

    int t  = threadIdx.x;
    int m0 = blockIdx.x * 128;
    int n    = m0 / HWSZ;
    int pix0 = m0 % HWSZ;
    int y0 = pix0 / WW, x0 = pix0 % WW;

    if (t < 512) {
        s_kb[t] = g_kb[t];
        s_vb[t] = g_vb[t];
    }
#pragma unroll 4
    for (int j = 0; j < 32; ++j) {
        int li = j * 512 + t;
        int c = li >> 7, m = li & 127;
        As[c * PAD + m] = feat[(size_t)(n * CC + c) * HWSZ + pix0 + m];
    }
#pragma unroll 4
    for (int j = 0; j < 32; ++j) {
        int li = j * 512 + t;
        int c = li >> 7, d = li & 127;
        Bs[c * PAD + d] = __uint_as_float(f2tf32(qw[li]));
    }
    __syncthreads();

    // Per-pixel sine PE added into As (2 threads/pixel)
    if (t < 256) {
        int m    = t >> 1;
        int half = t & 1;
        int pix  = pix0 + m;
        int yy = pix / WW, xx = pix % WW;
        const float* fl = flow + (size_t)((n * HH + yy) * WW + xx) * 2;
        float fx = fl[0], fy = fl[1];
        float full = half ? ((float)xx + fx) : ((float)yy + fy);
        float dec  = full - floorf(full);
        float base = dec * (6.283185307179586f / 2.000001f);
        int coff = half * 64;
#pragma unroll
        for (int t2 = 0; t2 < 32; ++t2) {
            float arg = base * inv_dt(t2);
            float s, c;
            sincosf(arg, &s, &c);
            As[(coff + 2 * t2)     * PAD + m] += s;
            As[(coff + 2 * t2 + 1) * PAD + m] += c;
        }
    }
    __syncthreads();

    // tf32-round As in place
#pragma unroll 4
    for (int j = 0; j < 32; ++j) {
        int li = j * 512 + t;
        int c = li >> 7, m = li & 127;
        As[c * PAD + m] = __uint_as_float(f2tf32(As[c * PAD + m]));
    }
    __syncthreads();

    int w = t >> 5, lane = t & 31;
    int m0w = (w & 3) * 32, n0w = (w >> 2) * 32;
    int q = lane & 3, g = lane >> 2;

    float acc[2][4][4];
#pragma unroll
    for (int mi = 0; mi < 2; ++mi)
#pragma unroll
        for (int nj = 0; nj < 4; ++nj)
#pragma unroll
            for (int e = 0; e < 4; ++e) acc[mi][nj][e] = 0.f;

#pragma unroll
    for (int kk = 0; kk < 16; ++kk) {
        int k0 = kk * 8;
        uint32_t a[2][4];
#pragma unroll
        for (int mi = 0; mi < 2; ++mi) {
            int m = m0w + mi * 16 + g;
            a[mi][0] = __float_as_uint(As[(k0 + q) * PAD + m]);
            a[mi][1] = __float_as_uint(As[(k0 + q) * PAD + m + 8]);
            a[mi][2] = __float_as_uint(As[(k0 + q + 4) * PAD + m]);
            a[mi][3] = __float_as_uint(As[(k0 + q + 4) * PAD + m + 8]);
        }
#pragma unroll
        for (int nj = 0; nj < 4; ++nj) {
            int nn = n0w + nj * 8 + g;
            uint32_t b0 = __float_as_uint(Bs[(k0 + q) * PAD + nn]);
            uint32_t b1 = __float_as_uint(Bs[(k0 + q + 4) * PAD + nn]);
#pragma unroll
            for (int mi = 0; mi < 2; ++mi)
                mma_tf32(acc[mi][nj], a[mi], b0, b1);
        }
    }
    __syncthreads();   // everyone done reading As/Bs

    // Qs = (acc + qb) * scale, into the As region
    float* Qs = As;    // [128][QPIT]
    const float sc = 0.25f;
#pragma unroll
    for (int mi = 0; mi < 2; ++mi) {
#pragma unroll
        for (int nj = 0; nj < 4; ++nj) {
            int r0 = m0w + mi * 16 + g;
            int cb = n0w + nj * 8 + q * 2;
            float b0 = qb[cb], b1 = qb[cb + 1];
            Qs[r0 * QPIT + cb]           = (acc[mi][nj][0] + b0) * sc;
            Qs[r0 * QPIT + cb + 1]       = (acc[mi][nj][1] + b1) * sc;
            Qs[(r0 + 8) * QPIT + cb]     = (acc[mi][nj][2] + b0) * sc;
            Qs[(r0 + 8) * QPIT + cb + 1] = (acc[mi][nj][3] + b1) * sc;
        }
    }
    __syncthreads();

    // Attention: warp-per-pixel, 16 warps x 8 iterations
    float* Os = Bs;    // [128][QPIT]
    int c0 = lane * 4;
#pragma unroll 1
    for (int it = 0; it < 8; ++it) {
        int ptile = it * 16 + w;
        int p   = m0 + ptile;
        int pix = pix0 + ptile;
        int yy = pix / WW, xx = pix % WW;

        const float* fl = flow + (size_t)((n * HH + yy) * WW + xx) * 2;
        float fx = fl[0], fy = fl[1];
        int giy = (int)floorf((float)yy + fy);
        int gix = (int)floorf((float)xx + fx);

        float4 qv = *(const float4*)(Qs + ptile * QPIT + c0);

        int   nb[4];
        float lg[4];
#pragma unroll
        for (int w2 = 0; w2 < 4; ++w2) {
            int hy = giy + (w2 >> 1);
            int wx = gix + (w2 & 1);
            hy = hy < 0 ? 0 : (hy > HH - 1 ? HH - 1 : hy);
            wx = wx < 0 ? 0 : (wx > WW - 1 ? WW - 1 : wx);
            nb[w2] = n * HWSZ + hy * WW + wx;
            float4 k = *(const float4*)(g_K + (size_t)nb[w2] * DIM + c0);
            const float* kbp = s_kb + w2 * DIM + c0;
            float part = qv.x * (k.x + kbp[0]) + qv.y * (k.y + kbp[1]) +
                         qv.z * (k.z + kbp[2]) + qv.w * (k.w + kbp[3]);
            part += __shfl_xor_sync(0xffffffffu, part, 1);
            part += __shfl_xor_sync(0xffffffffu, part, 2);
            lg[w2] = part;
        }
        float mx = fmaxf(fmaxf(lg[0], lg[1]), fmaxf(lg[2], lg[3]));
        float e0 = expf(lg[0] - mx), e1 = expf(lg[1] - mx);
        float e2 = expf(lg[2] - mx), e3 = expf(lg[3] - mx);
        float inv = 1.f / (e0 + e1 + e2 + e3);
        float aw[4] = {e0 * inv, e1 * inv, e2 * inv, e3 * inv};

        float4 o = make_float4(0.f, 0.f, 0.f, 0.f);
#pragma unroll
        for (int w2 = 0; w2 < 4; ++w2) {
            float4 v = *(const float4*)(g_V + (size_t)nb[w2] * DIM + c0);
            const float* vbp = s_vb + w2 * DIM + c0;
            float a = aw[w2];
            o.x += a * (v.x + vbp[0]);
            o.y += a * (v.y + vbp[1]);
            o.z += a * (v.z + vbp[2]);
            o.w += a * (v.w + vbp[3]);
        }
        *(float4*)(Os + ptile * QPIT + c0) = o;
    }
    __syncthreads();

    // Coalesced channel-major writes: out[n][d][y0][x0 + px]
#pragma unroll 4
    for (int j = 0; j < 32; ++j) {
        int li = j * 512 + t;
        int d  = li >> 7, px = li & 127;
        out[((size_t)(n * DIM + d) * HH + y0) * WW + x0 + px] = Os[px * QPIT + d];
    }
}

// ---------------------------------------------------------------------------
extern "C" void kernel_launch(void* const* d_in, const int* in_sizes, int n_in,
                              void* d_out, int out_size) {
    const float* feat_supp = (const float*)d_in[0];
    const float* feat_curr = (const float*)d_in[1];
    const float* flow      = (const float*)d_in[2];
    const float* q_w       = (const float*)d_in[3];
    const float* q_b       = (const float*)d_in[4];
    const float* k_w       = (const float*)d_in[5];
    const float* k_b       = (const float*)d_in[6];
    const float* v_w       = (const float*)d_in[7];
    const float* v_b       = (const float*)d_in[8];
    float* out = (float*)d_out;

    const int smem_kv = 3 * 128 * PAD * (int)sizeof(float);  // 208896 B
    const int smem_q  = 2 * 128 * PAD * (int)sizeof(float);  // 139264 B
    cudaFuncSetAttribute(gemm_kv_kernel, cudaFuncAttributeMaxDynamicSharedMemorySize, smem_kv);
    cudaFuncSetAttribute(q_attn_kernel,  cudaFuncAttributeMaxDynamicSharedMemorySize, smem_q);

    bias_kernel<<<1, 512>>>(k_w, k_b, v_w, v_b);
    gemm_kv_kernel<<<NHW / 128, 512, smem_kv>>>(feat_supp, k_w, v_w);
    q_attn_kernel<<<NHW / 128, 512, smem_q>>>(feat_curr, flow, q_w, q_b, out);
}

// round 4
// speedup vs baseline: 1.4355x; 1.4355x over previous
#include <cuda_runtime.h>
#include <math.h>
#include <stdint.h>

// Problem constants
#define NB   4
#define CC   128
#define HH   128
#define WW   256
#define HWSZ (HH * WW)          // 32768
#define NHW  (NB * HWSZ)        // 131072
#define DIM  128
#define NWP  4
#define PAD  136                // smem row pitch (words); 136%32==8 -> conflict-free frags

// Device-global scratch
__device__ float g_K[(size_t)NHW * DIM];
__device__ float g_V[(size_t)NHW * DIM];
__device__ float g_Q[(size_t)NHW * DIM];
__device__ float g_kb[NWP * DIM];
__device__ float g_vb[NWP * DIM];

__device__ __forceinline__ float inv_dt(int t2) {
    return exp2f(-(float)t2 * (13.287712379549449f / 32.0f));
}

__device__ __forceinline__ void cp16(uint32_t saddr, const void* g) {
    asm volatile("cp.async.cg.shared.global [%0], [%1], 16;" :: "r"(saddr), "l"(g));
}
__device__ __forceinline__ void cp_commit_wait() {
    asm volatile("cp.async.commit_group;\ncp.async.wait_group 0;" ::: "memory");
}

// tf32 mma; operands are raw fp32 bit patterns (HW truncates low mantissa)
__device__ __forceinline__ void mma_tf32(float d[4], const uint32_t a[4],
                                         uint32_t b0, uint32_t b1) {
    asm volatile(
        "mma.sync.aligned.m16n8k8.row.col.f32.tf32.tf32.f32 "
        "{%0,%1,%2,%3}, {%4,%5,%6,%7}, {%8,%9}, {%0,%1,%2,%3};\n"
        : "+f"(d[0]), "+f"(d[1]), "+f"(d[2]), "+f"(d[3])
        : "r"(a[0]), "r"(a[1]), "r"(a[2]), "r"(a[3]), "r"(b0), "r"(b1));
}

// ---------------------------------------------------------------------------
// Kernel 0: window position-bias projections. 8 CTAs:
//   blockIdx.x = matrix*4 + w  (matrix 0=K, 1=V; w = window index)
// 512 threads: 4 threads per output d (split-K over 32 channels each).
// ---------------------------------------------------------------------------
__global__ void bias_kernel(const float* __restrict__ kw, const float* __restrict__ kb,
                            const float* __restrict__ vw, const float* __restrict__ vb) {
    __shared__ float pb[DIM];
    int t = threadIdx.x;
    int w      = blockIdx.x & 3;
    int matrix = blockIdx.x >> 2;
    if (t < DIM) {
        int oy = w >> 1, ox = w & 1;
        float coord = (t < 64) ? (float)oy : (float)ox;
        int ii = t & 63;
        int t2 = ii >> 1;
        float arg = coord * (6.283185307179586f / 1.000001f) * inv_dt(t2);
        float s, c;
        sincosf(arg, &s, &c);
        pb[t] = (ii & 1) ? c : s;
    }
    __syncthreads();

    const float* W  = matrix ? vw : kw;
    const float* Bb = matrix ? vb : kb;
    float* dst      = matrix ? g_vb : g_kb;

    int d = t >> 2, q = t & 3;
    float acc = 0.f;
    int cbase = q * 32;
#pragma unroll 8
    for (int c = 0; c < 32; ++c)
        acc += pb[cbase + c] * W[(cbase + c) * DIM + d];
    acc += __shfl_xor_sync(0xffffffffu, acc, 1);
    acc += __shfl_xor_sync(0xffffffffu, acc, 2);
    if (q == 0)
        dst[w * DIM + d] = acc + Bb[d];
}

// ---------------------------------------------------------------------------
// Kernel 1: g_K = feat_supp @ k_w ; g_V = feat_supp @ v_w (tf32 mma.sync)
// Fills via cp.async (raw fp32; no cvt).
// ---------------------------------------------------------------------------
__global__ __launch_bounds__(512, 1)
void gemm_kv_kernel(const float* __restrict__ feat,
                    const float* __restrict__ kw,
                    const float* __restrict__ vw) {
    extern __shared__ float sm[];
    float* As = sm;
    float* Bk = sm + 128 * PAD;
    float* Bv = sm + 2 * 128 * PAD;
    uint32_t As_u = (uint32_t)__cvta_generic_to_shared(As);
    uint32_t Bk_u = (uint32_t)__cvta_generic_to_shared(Bk);
    uint32_t Bv_u = (uint32_t)__cvta_generic_to_shared(Bv);
    int t  = threadIdx.x;
    int m0 = blockIdx.x * 128;
    int n    = m0 / HWSZ;
    int pix0 = m0 % HWSZ;

#pragma unroll
    for (int j = 0; j < 8; ++j) {
        int li = j * 512 + t;
        int c = li >> 5, mv = li & 31;
        cp16(As_u + (c * PAD + mv * 4) * 4,
             feat + (size_t)(n * CC + c) * HWSZ + pix0 + mv * 4);
    }
#pragma unroll
    for (int j = 0; j < 8; ++j) {
        int li = j * 512 + t;
        int c = li >> 5, dv = li & 31;
        cp16(Bk_u + (c * PAD + dv * 4) * 4, kw + c * DIM + dv * 4);
        cp16(Bv_u + (c * PAD + dv * 4) * 4, vw + c * DIM + dv * 4);
    }
    cp_commit_wait();
    __syncthreads();

    int w = t >> 5, lane = t & 31;
    int m0w = (w & 3) * 32, n0w = (w >> 2) * 32;
    int q = lane & 3, g = lane >> 2;

    float accK[2][4][4];
    float accV[2][4][4];
#pragma unroll
    for (int mi = 0; mi < 2; ++mi)
#pragma unroll
        for (int nj = 0; nj < 4; ++nj)
#pragma unroll
            for (int e = 0; e < 4; ++e) { accK[mi][nj][e] = 0.f; accV[mi][nj][e] = 0.f; }

#pragma unroll
    for (int kk = 0; kk < 16; ++kk) {
        int k0 = kk * 8;
        uint32_t a[2][4];
#pragma unroll
        for (int mi = 0; mi < 2; ++mi) {
            int m = m0w + mi * 16 + g;
            a[mi][0] = __float_as_uint(As[(k0 + q) * PAD + m]);
            a[mi][1] = __float_as_uint(As[(k0 + q) * PAD + m + 8]);
            a[mi][2] = __float_as_uint(As[(k0 + q + 4) * PAD + m]);
            a[mi][3] = __float_as_uint(As[(k0 + q + 4) * PAD + m + 8]);
        }
#pragma unroll
        for (int nj = 0; nj < 4; ++nj) {
            int nn = n0w + nj * 8 + g;
            uint32_t bk0 = __float_as_uint(Bk[(k0 + q) * PAD + nn]);
            uint32_t bk1 = __float_as_uint(Bk[(k0 + q + 4) * PAD + nn]);
            uint32_t bv0 = __float_as_uint(Bv[(k0 + q) * PAD + nn]);
            uint32_t bv1 = __float_as_uint(Bv[(k0 + q + 4) * PAD + nn]);
#pragma unroll
            for (int mi = 0; mi < 2; ++mi) {
                mma_tf32(accK[mi][nj], a[mi], bk0, bk1);
                mma_tf32(accV[mi][nj], a[mi], bv0, bv1);
            }
        }
    }

#pragma unroll
    for (int mi = 0; mi < 2; ++mi) {
#pragma unroll
        for (int nj = 0; nj < 4; ++nj) {
            int r0 = m0 + m0w + mi * 16 + g;
            int cb = n0w + nj * 8 + q * 2;
            *(float2*)(g_K + (size_t)r0 * DIM + cb) =
                make_float2(accK[mi][nj][0], accK[mi][nj][1]);
            *(float2*)(g_K + (size_t)(r0 + 8) * DIM + cb) =
                make_float2(accK[mi][nj][2], accK[mi][nj][3]);
            *(float2*)(g_V + (size_t)r0 * DIM + cb) =
                make_float2(accV[mi][nj][0], accV[mi][nj][1]);
            *(float2*)(g_V + (size_t)(r0 + 8) * DIM + cb) =
                make_float2(accV[mi][nj][2], accV[mi][nj][3]);
        }
    }
}

// ---------------------------------------------------------------------------
// Kernel 2: g_Q = (feat_curr + PE(frac(flow))) @ q_w + q_b  (tf32 mma.sync)
// ---------------------------------------------------------------------------
__global__ __launch_bounds__(512, 1)
void gemm_q_kernel(const float* __restrict__ feat,
                   const float* __restrict__ flow,
                   const float* __restrict__ qw,
                   const float* __restrict__ qb) {
    extern __shared__ float sm[];
    float* As = sm;
    float* Bs = sm + 128 * PAD;
    uint32_t As_u = (uint32_t)__cvta_generic_to_shared(As);
    uint32_t Bs_u = (uint32_t)__cvta_generic_to_shared(Bs);
    int t  = threadIdx.x;
    int m0 = blockIdx.x * 128;
    int n    = m0 / HWSZ;
    int pix0 = m0 % HWSZ;

#pragma unroll
    for (int j = 0; j < 8; ++j) {
        int li = j * 512 + t;
        int c = li >> 5, mv = li & 31;
        cp16(As_u + (c * PAD + mv * 4) * 4,
             feat + (size_t)(n * CC + c) * HWSZ + pix0 + mv * 4);
    }
#pragma unroll
    for (int j = 0; j < 8; ++j) {
        int li = j * 512 + t;
        int c = li >> 5, dv = li & 31;
        cp16(Bs_u + (c * PAD + dv * 4) * 4, qw + c * DIM + dv * 4);
    }
    cp_commit_wait();
    __syncthreads();

    // Per-pixel sine PE added into As (2 threads/pixel)
    if (t < 256) {
        int m    = t >> 1;
        int half = t & 1;
        int pix  = pix0 + m;
        int yy = pix / WW, xx = pix % WW;
        const float* fl = flow + (size_t)((n * HH + yy) * WW + xx) * 2;
        float fx = fl[0], fy = fl[1];
        float full = half ? ((float)xx + fx) : ((float)yy + fy);
        float dec  = full - floorf(full);
        float base = dec * (6.283185307179586f / 2.000001f);
        int coff = half * 64;
#pragma unroll
        for (int t2 = 0; t2 < 32; ++t2) {
            float arg = base * inv_dt(t2);
            float s, c;
            sincosf(arg, &s, &c);
            As[(coff + 2 * t2)     * PAD + m] += s;
            As[(coff + 2 * t2 + 1) * PAD + m] += c;
        }
    }
    __syncthreads();

    int w = t >> 5, lane = t & 31;
    int m0w = (w & 3) * 32, n0w = (w >> 2) * 32;
    int q = lane & 3, g = lane >> 2;

    float acc[2][4][4];
#pragma unroll
    for (int mi = 0; mi < 2; ++mi)
#pragma unroll
        for (int nj = 0; nj < 4; ++nj)
#pragma unroll
            for (int e = 0; e < 4; ++e) acc[mi][nj][e] = 0.f;

#pragma unroll
    for (int kk = 0; kk < 16; ++kk) {
        int k0 = kk * 8;
        uint32_t a[2][4];
#pragma unroll
        for (int mi = 0; mi < 2; ++mi) {
            int m = m0w + mi * 16 + g;
            a[mi][0] = __float_as_uint(As[(k0 + q) * PAD + m]);
            a[mi][1] = __float_as_uint(As[(k0 + q) * PAD + m + 8]);
            a[mi][2] = __float_as_uint(As[(k0 + q + 4) * PAD + m]);
            a[mi][3] = __float_as_uint(As[(k0 + q + 4) * PAD + m + 8]);
        }
#pragma unroll
        for (int nj = 0; nj < 4; ++nj) {
            int nn = n0w + nj * 8 + g;
            uint32_t b0 = __float_as_uint(Bs[(k0 + q) * PAD + nn]);
            uint32_t b1 = __float_as_uint(Bs[(k0 + q + 4) * PAD + nn]);
#pragma unroll
            for (int mi = 0; mi < 2; ++mi)
                mma_tf32(acc[mi][nj], a[mi], b0, b1);
        }
    }

#pragma unroll
    for (int mi = 0; mi < 2; ++mi) {
#pragma unroll
        for (int nj = 0; nj < 4; ++nj) {
            int r0 = m0 + m0w + mi * 16 + g;
            int cb = n0w + nj * 8 + q * 2;
            float b0 = qb[cb], b1 = qb[cb + 1];
            *(float2*)(g_Q + (size_t)r0 * DIM + cb) =
                make_float2(acc[mi][nj][0] + b0, acc[mi][nj][1] + b1);
            *(float2*)(g_Q + (size_t)(r0 + 8) * DIM + cb) =
                make_float2(acc[mi][nj][2] + b0, acc[mi][nj][3] + b1);
        }
    }
}

// ---------------------------------------------------------------------------
// Kernel 3: per-pixel attention (R1/R2 proven version)
// ---------------------------------------------------------------------------
__global__ void attn_kernel(const float* __restrict__ flow, float* __restrict__ out) {
    __shared__ float s_out[8][132];
    __shared__ float s_kb[NWP * DIM];
    __shared__ float s_vb[NWP * DIM];
    int t = threadIdx.x;
    for (int i = t; i < NWP * DIM; i += 256) {
        s_kb[i] = g_kb[i];
        s_vb[i] = g_vb[i];
    }
    __syncthreads();

    int warp = t >> 5, lane = t & 31;
    int p   = blockIdx.x * 8 + warp;
    int n   = p / HWSZ;
    int pix = p % HWSZ;
    int y = pix / WW, x = pix % WW;

    const float* fl = flow + (size_t)((n * HH + y) * WW + x) * 2;
    float fx = fl[0], fy = fl[1];
    int giy = (int)floorf((float)y + fy);
    int gix = (int)floorf((float)x + fx);

    int c0 = lane * 4;
    float4 qv = *(const float4*)(g_Q + (size_t)p * DIM + c0);
    const float sc = 0.25f;
    qv.x *= sc; qv.y *= sc; qv.z *= sc; qv.w *= sc;

    int   nb[4];
    float lg[4];
#pragma unroll
    for (int w2 = 0; w2 < 4; ++w2) {
        int hy = giy + (w2 >> 1);
        int wx = gix + (w2 & 1);
        hy = hy < 0 ? 0 : (hy > HH - 1 ? HH - 1 : hy);
        wx = wx < 0 ? 0 : (wx > WW - 1 ? WW - 1 : wx);
        nb[w2] = n * HWSZ + hy * WW + wx;
        float4 k = *(const float4*)(g_K + (size_t)nb[w2] * DIM + c0);
        const float* kbp = s_kb + w2 * DIM + c0;
        float part = qv.x * (k.x + kbp[0]) + qv.y * (k.y + kbp[1]) +
                     qv.z * (k.z + kbp[2]) + qv.w * (k.w + kbp[3]);
        part += __shfl_xor_sync(0xffffffffu, part, 1);
        part += __shfl_xor_sync(0xffffffffu, part, 2);
        lg[w2] = part;
    }
    float mx = fmaxf(fmaxf(lg[0], lg[1]), fmaxf(lg[2], lg[3]));
    float e0 = __expf(lg[0] - mx), e1 = __expf(lg[1] - mx);
    float e2 = __expf(lg[2] - mx), e3 = __expf(lg[3] - mx);
    float inv = 1.f / (e0 + e1 + e2 + e3);
    float aw[4] = {e0 * inv, e1 * inv, e2 * inv, e3 * inv};

    float4 o = make_float4(0.f, 0.f, 0.f, 0.f);
#pragma unroll
    for (int w2 = 0; w2 < 4; ++w2) {
        float4 v = *(const float4*)(g_V + (size_t)nb[w2] * DIM + c0);
        const float* vbp = s_vb + w2 * DIM + c0;
        float a = aw[w2];
        o.x += a * (v.x + vbp[0]);
        o.y += a * (v.y + vbp[1]);
        o.z += a * (v.z + vbp[2]);
        o.w += a * (v.w + vbp[3]);
    }
    s_out[warp][c0 + 0] = o.x;
    s_out[warp][c0 + 1] = o.y;
    s_out[warp][c0 + 2] = o.z;
    s_out[warp][c0 + 3] = o.w;
    __syncthreads();

    int p0   = blockIdx.x * 8;
    int n0   = p0 / HWSZ;
    int pix0 = p0 % HWSZ;
    int y0 = pix0 / WW, x0 = pix0 % WW;
#pragma unroll
    for (int rep = 0; rep < 4; ++rep) {
        int d  = (t >> 3) + rep * 32;
        int px = t & 7;
        out[((size_t)(n0 * DIM + d) * HH + y0) * WW + x0 + px] = s_out[px][d];
    }
}

// ---------------------------------------------------------------------------
extern "C" void kernel_launch(void* const* d_in, const int* in_sizes, int n_in,
                              void* d_out, int out_size) {
    const float* feat_supp = (const float*)d_in[0];
    const float* feat_curr = (const float*)d_in[1];
    const float* flow      = (const float*)d_in[2];
    const float* q_w       = (const float*)d_in[3];
    const float* q_b       = (const float*)d_in[4];
    const float* k_w       = (const float*)d_in[5];
    const float* k_b       = (const float*)d_in[6];
    const float* v_w       = (const float*)d_in[7];
    const float* v_b       = (const float*)d_in[8];
    float* out = (float*)d_out;

    const int smem_kv = 3 * 128 * PAD * (int)sizeof(float);  // 208896 B
    const int smem_q  = 2 * 128 * PAD * (int)sizeof(float);  // 139264 B
    cudaFuncSetAttribute(gemm_kv_kernel, cudaFuncAttributeMaxDynamicSharedMemorySize, smem_kv);
    cudaFuncSetAttribute(gemm_q_kernel,  cudaFuncAttributeMaxDynamicSharedMemorySize, smem_q);

    bias_kernel<<<8, 512>>>(k_w, k_b, v_w, v_b);
    gemm_kv_kernel<<<NHW / 128, 512, smem_kv>>>(feat_supp, k_w, v_w);
    gemm_q_kernel<<<NHW / 128, 512, smem_q>>>(feat_curr, flow, q_w, q_b);
    attn_kernel<<<NHW / 8, 256>>>(flow, out);
}

// round 5
// speedup vs baseline: 1.5649x; 1.0901x over previous
#include <cuda_runtime.h>
#include <math.h>
#include <stdint.h>

// Problem constants
#define NB   4
#define CC   128
#define HH   128
#define WW   256
#define HWSZ (HH * WW)          // 32768
#define NHW  (NB * HWSZ)        // 131072
#define DIM  128
#define NWP  4
#define APIT 136                // A smem pitch (words); %32==8 -> conflict-free frags
#define BPIT 264                // fused K|V B-panel pitch; %32==8
#define SKV  (32 * APIT + 32 * BPIT)   // words per kv stage = 12800
#define SQ   (32 * APIT + 32 * APIT)   // words per q stage  = 8704

// Device-global scratch
__device__ float g_K[(size_t)NHW * DIM];
__device__ float g_V[(size_t)NHW * DIM];
__device__ float g_Q[(size_t)NHW * DIM];
__device__ float g_kb[NWP * DIM];
__device__ float g_vb[NWP * DIM];

__device__ __forceinline__ float inv_dt(int t2) {
    return exp2f(-(float)t2 * (13.287712379549449f / 32.0f));
}

__device__ __forceinline__ void cp16(uint32_t saddr, const void* g) {
    asm volatile("cp.async.cg.shared.global [%0], [%1], 16;" :: "r"(saddr), "l"(g));
}
__device__ __forceinline__ void cp_commit() {
    asm volatile("cp.async.commit_group;" ::: "memory");
}
template<int N> __device__ __forceinline__ void cp_wait() {
    asm volatile("cp.async.wait_group %0;" :: "n"(N) : "memory");
}

// tf32 mma; operands raw fp32 bit patterns (HW truncates mantissa)
__device__ __forceinline__ void mma_tf32(float d[4], const uint32_t a[4],
                                         uint32_t b0, uint32_t b1) {
    asm volatile(
        "mma.sync.aligned.m16n8k8.row.col.f32.tf32.tf32.f32 "
        "{%0,%1,%2,%3}, {%4,%5,%6,%7}, {%8,%9}, {%0,%1,%2,%3};\n"
        : "+f"(d[0]), "+f"(d[1]), "+f"(d[2]), "+f"(d[3])
        : "r"(a[0]), "r"(a[1]), "r"(a[2]), "r"(a[3]), "r"(b0), "r"(b1));
}

// ---------------------------------------------------------------------------
// Kernel 0: window position-bias projections (8 CTAs, shfl split-K)
// ---------------------------------------------------------------------------
__global__ void bias_kernel(const float* __restrict__ kw, const float* __restrict__ kb,
                            const float* __restrict__ vw, const float* __restrict__ vb) {
    __shared__ float pb[DIM];
    int t = threadIdx.x;
    int w      = blockIdx.x & 3;
    int matrix = blockIdx.x >> 2;
    if (t < DIM) {
        int oy = w >> 1, ox = w & 1;
        float coord = (t < 64) ? (float)oy : (float)ox;
        int ii = t & 63;
        int t2 = ii >> 1;
        float arg = coord * (6.283185307179586f / 1.000001f) * inv_dt(t2);
        float s, c;
        sincosf(arg, &s, &c);
        pb[t] = (ii & 1) ? c : s;
    }
    __syncthreads();

    const float* W  = matrix ? vw : kw;
    const float* Bb = matrix ? vb : kb;
    float* dst      = matrix ? g_vb : g_kb;

    int d = t >> 2, q = t & 3;
    float acc = 0.f;
    int cbase = q * 32;
#pragma unroll 8
    for (int c = 0; c < 32; ++c)
        acc += pb[cbase + c] * W[(cbase + c) * DIM + d];
    acc += __shfl_xor_sync(0xffffffffu, acc, 1);
    acc += __shfl_xor_sync(0xffffffffu, acc, 2);
    if (q == 0)
        dst[w * DIM + d] = acc + Bb[d];
}

// ---------------------------------------------------------------------------
// Kernel 1: fused g_K / g_V GEMM, 3-stage cp.async pipeline over BK=32 chunks.
// B panel = [kw | vw] 256 cols. 16 warps, warp tile m32 x n64.
// ---------------------------------------------------------------------------
struct KVFill {
    uint32_t sm_u;
    const float *feat, *kw, *vw;
    int n, pix0, t;
    __device__ __forceinline__ void operator()(int chunk, int stg) const {
        uint32_t As_u = sm_u + (uint32_t)(stg * SKV) * 4u;
        uint32_t Bs_u = As_u + 32 * APIT * 4;
        int kb = chunk * 32;
#pragma unroll
        for (int j = 0; j < 2; ++j) {
            int li = j * 512 + t;
            int r = li >> 5, m4 = li & 31;
            cp16(As_u + (r * APIT + m4 * 4) * 4,
                 feat + (size_t)(n * CC + kb + r) * HWSZ + pix0 + m4 * 4);
        }
#pragma unroll
        for (int j = 0; j < 4; ++j) {
            int li = j * 512 + t;
            int r = li >> 6, d4 = li & 63;
            const float* src = (d4 < 32) ? (kw + (kb + r) * DIM + d4 * 4)
                                         : (vw + (kb + r) * DIM + (d4 - 32) * 4);
            int col = (d4 < 32) ? (d4 * 4) : (128 + (d4 - 32) * 4);
            cp16(Bs_u + (r * BPIT + col) * 4, src);
        }
    }
};

__device__ __forceinline__ void mma_chunk_kv(const float* __restrict__ As,
                                             const float* __restrict__ Bs,
                                             float acc[2][8][4],
                                             int m0w, int n0w, int q, int g) {
#pragma unroll
    for (int ks = 0; ks < 4; ++ks) {
        int k0 = ks * 8;
        uint32_t a[2][4];
#pragma unroll
        for (int mi = 0; mi < 2; ++mi) {
            int m = m0w + mi * 16 + g;
            a[mi][0] = __float_as_uint(As[(k0 + q) * APIT + m]);
            a[mi][1] = __float_as_uint(As[(k0 + q) * APIT + m + 8]);
            a[mi][2] = __float_as_uint(As[(k0 + q + 4) * APIT + m]);
            a[mi][3] = __float_as_uint(As[(k0 + q + 4) * APIT + m + 8]);
        }
#pragma unroll
        for (int nj = 0; nj < 8; ++nj) {
            int nn = n0w + nj * 8 + g;
            uint32_t b0 = __float_as_uint(Bs[(k0 + q) * BPIT + nn]);
            uint32_t b1 = __float_as_uint(Bs[(k0 + q + 4) * BPIT + nn]);
#pragma unroll
            for (int mi = 0; mi < 2; ++mi)
                mma_tf32(acc[mi][nj], a[mi], b0, b1);
        }
    }
}

__global__ __launch_bounds__(512, 1)
void gemm_kv_kernel(const float* __restrict__ feat,
                    const float* __restrict__ kw,
                    const float* __restrict__ vw) {
    extern __shared__ float sm[];
    uint32_t sm_u = (uint32_t)__cvta_generic_to_shared(sm);
    int t  = threadIdx.x;
    int m0 = blockIdx.x * 128;
    int n    = m0 / HWSZ;
    int pix0 = m0 % HWSZ;

    KVFill fill{sm_u, feat, kw, vw, n, pix0, t};

    fill(0, 0); cp_commit();
    fill(1, 1); cp_commit();
    fill(2, 2); cp_commit();

    int w = t >> 5, lane = t & 31;
    int m0w = (w & 3) * 32, n0w = (w >> 2) * 64;
    int q = lane & 3, g = lane >> 2;

    float acc[2][8][4];
#pragma unroll
    for (int mi = 0; mi < 2; ++mi)
#pragma unroll
        for (int nj = 0; nj < 8; ++nj)
#pragma unroll
            for (int e = 0; e < 4; ++e) acc[mi][nj][e] = 0.f;

    float* st0 = sm;
    float* st1 = sm + SKV;
    float* st2 = sm + 2 * SKV;

    cp_wait<2>(); __syncthreads();
    mma_chunk_kv(st0, st0 + 32 * APIT, acc, m0w, n0w, q, g);
    __syncthreads();
    fill(3, 0); cp_commit();
    cp_wait<2>(); __syncthreads();
    mma_chunk_kv(st1, st1 + 32 * APIT, acc, m0w, n0w, q, g);
    cp_wait<1>(); __syncthreads();
    mma_chunk_kv(st2, st2 + 32 * APIT, acc, m0w, n0w, q, g);
    cp_wait<0>(); __syncthreads();
    mma_chunk_kv(st0, st0 + 32 * APIT, acc, m0w, n0w, q, g);

    // Epilogue: cols <128 -> g_K, else g_V
#pragma unroll
    for (int mi = 0; mi < 2; ++mi) {
#pragma unroll
        for (int nj = 0; nj < 8; ++nj) {
            int r0 = m0 + m0w + mi * 16 + g;
            int col = n0w + nj * 8 + q * 2;
            float* dst = (col < 128) ? (g_K + (size_t)r0 * DIM + col)
                                     : (g_V + (size_t)r0 * DIM + (col - 128));
            *(float2*)dst = make_float2(acc[mi][nj][0], acc[mi][nj][1]);
            *(float2*)(dst + (size_t)8 * DIM) = make_float2(acc[mi][nj][2], acc[mi][nj][3]);
        }
    }
}

// ---------------------------------------------------------------------------
// Kernel 2: g_Q = (feat_curr + PE(frac(flow))) @ q_w + q_b, pipelined.
// PE added per chunk in smem (one sincos per sin/cos channel pair).
// ---------------------------------------------------------------------------
struct QFill {
    uint32_t sm_u;
    const float *feat, *qw;
    int n, pix0, t;
    __device__ __forceinline__ void operator()(int chunk, int stg) const {
        uint32_t As_u = sm_u + (uint32_t)(stg * SQ) * 4u;
        uint32_t Bs_u = As_u + 32 * APIT * 4;
        int kb = chunk * 32;
#pragma unroll
        for (int j = 0; j < 2; ++j) {
            int li = j * 512 + t;
            int r = li >> 5, m4 = li & 31;
            cp16(As_u + (r * APIT + m4 * 4) * 4,
                 feat + (size_t)(n * CC + kb + r) * HWSZ + pix0 + m4 * 4);
        }
#pragma unroll
        for (int j = 0; j < 2; ++j) {
            int li = j * 512 + t;
            int r = li >> 5, d4 = li & 31;
            cp16(Bs_u + (r * APIT + d4 * 4) * 4, qw + (kb + r) * DIM + d4 * 4);
        }
    }
};

__device__ __forceinline__ void pe_chunk(float* __restrict__ As, int kb,
                                         const float* __restrict__ s_base,
                                         const float* __restrict__ s_idt, int t) {
    // 16 channel-pairs x 128 pixels per chunk; 4 per thread
#pragma unroll
    for (int j = 0; j < 4; ++j) {
        int li = j * 512 + t;
        int pi = li >> 7, m = li & 127;
        int c0 = kb + pi * 2;                 // even channel
        int half = (c0 >> 6) & 1;
        int t2 = (c0 & 63) >> 1;
        float arg = s_base[half * 128 + m] * s_idt[t2];
        float s, c;
        sincosf(arg, &s, &c);
        As[(pi * 2) * APIT + m]     += s;
        As[(pi * 2 + 1) * APIT + m] += c;
    }
}

__device__ __forceinline__ void mma_chunk_q(const float* __restrict__ As,
                                            const float* __restrict__ Bs,
                                            float acc[2][4][4],
                                            int m0w, int n0w, int q, int g) {
#pragma unroll
    for (int ks = 0; ks < 4; ++ks) {
        int k0 = ks * 8;
        uint32_t a[2][4];
#pragma unroll
        for (int mi = 0; mi < 2; ++mi) {
            int m = m0w + mi * 16 + g;
            a[mi][0] = __float_as_uint(As[(k0 + q) * APIT + m]);
            a[mi][1] = __float_as_uint(As[(k0 + q) * APIT + m + 8]);
            a[mi][2] = __float_as_uint(As[(k0 + q + 4) * APIT + m]);
            a[mi][3] = __float_as_uint(As[(k0 + q + 4) * APIT + m + 8]);
        }
#pragma unroll
        for (int nj = 0; nj < 4; ++nj) {
            int nn = n0w + nj * 8 + g;
            uint32_t b0 = __float_as_uint(Bs[(k0 + q) * APIT + nn]);
            uint32_t b1 = __float_as_uint(Bs[(k0 + q + 4) * APIT + nn]);
#pragma unroll
            for (int mi = 0; mi < 2; ++mi)
                mma_tf32(acc[mi][nj], a[mi], b0, b1);
        }
    }
}

__global__ __launch_bounds__(512, 1)
void gemm_q_kernel(const float* __restrict__ feat,
                   const float* __restrict__ flow,
                   const float* __restrict__ qw,
                   const float* __restrict__ qb) {
    extern __shared__ float sm[];
    __shared__ float s_base[2 * 128];
    __shared__ float s_idt[32];
    uint32_t sm_u = (uint32_t)__cvta_generic_to_shared(sm);
    int t  = threadIdx.x;
    int m0 = blockIdx.x * 128;
    int n    = m0 / HWSZ;
    int pix0 = m0 % HWSZ;

    QFill fill{sm_u, feat, qw, n, pix0, t};
    fill(0, 0); cp_commit();
    fill(1, 1); cp_commit();
    fill(2, 2); cp_commit();

    // base angles + inv_dt table (overlapped with cp.async)
    if (t < 32) s_idt[t] = inv_dt(t);
    if (t < 256) {
        int m    = t >> 1;
        int half = t & 1;
        int pix  = pix0 + m;
        int yy = pix / WW, xx = pix % WW;
        const float* fl = flow + (size_t)((n * HH + yy) * WW + xx) * 2;
        float fx = fl[0], fy = fl[1];
        float full = half ? ((float)xx + fx) : ((float)yy + fy);
        float dec  = full - floorf(full);
        s_base[half * 128 + m] = dec * (6.283185307179586f / 2.000001f);
    }

    int w = t >> 5, lane = t & 31;
    int m0w = (w & 3) * 32, n0w = (w >> 2) * 32;
    int q = lane & 3, g = lane >> 2;

    float acc[2][4][4];
#pragma unroll
    for (int mi = 0; mi < 2; ++mi)
#pragma unroll
        for (int nj = 0; nj < 4; ++nj)
#pragma unroll
            for (int e = 0; e < 4; ++e) acc[mi][nj][e] = 0.f;

    float* st0 = sm;
    float* st1 = sm + SQ;
    float* st2 = sm + 2 * SQ;

    // chunk 0
    cp_wait<2>(); __syncthreads();
    pe_chunk(st0, 0, s_base, s_idt, t);
    __syncthreads();
    mma_chunk_q(st0, st0 + 32 * APIT, acc, m0w, n0w, q, g);
    __syncthreads();
    fill(3, 0); cp_commit();
    // chunk 1
    cp_wait<2>(); __syncthreads();
    pe_chunk(st1, 32, s_base, s_idt, t);
    __syncthreads();
    mma_chunk_q(st1, st1 + 32 * APIT, acc, m0w, n0w, q, g);
    // chunk 2
    cp_wait<1>(); __syncthreads();
    pe_chunk(st2, 64, s_base, s_idt, t);
    __syncthreads();
    mma_chunk_q(st2, st2 + 32 * APIT, acc, m0w, n0w, q, g);
    // chunk 3
    cp_wait<0>(); __syncthreads();
    pe_chunk(st0, 96, s_base, s_idt, t);
    __syncthreads();
    mma_chunk_q(st0, st0 + 32 * APIT, acc, m0w, n0w, q, g);

#pragma unroll
    for (int mi = 0; mi < 2; ++mi) {
#pragma unroll
        for (int nj = 0; nj < 4; ++nj) {
            int r0 = m0 + m0w + mi * 16 + g;
            int cb = n0w + nj * 8 + q * 2;
            float b0 = qb[cb], b1 = qb[cb + 1];
            *(float2*)(g_Q + (size_t)r0 * DIM + cb) =
                make_float2(acc[mi][nj][0] + b0, acc[mi][nj][1] + b1);
            *(float2*)(g_Q + (size_t)(r0 + 8) * DIM + cb) =
                make_float2(acc[mi][nj][2] + b0, acc[mi][nj][3] + b1);
        }
    }
}

// ---------------------------------------------------------------------------
// Kernel 3: per-pixel attention; all 8 K/V rows loaded before reductions (MLP)
// ---------------------------------------------------------------------------
__global__ void attn_kernel(const float* __restrict__ flow, float* __restrict__ out) {
    __shared__ float s_out[8][132];
    __shared__ float s_kb[NWP * DIM];
    __shared__ float s_vb[NWP * DIM];
    int t = threadIdx.x;
    for (int i = t; i < NWP * DIM; i += 256) {
        s_kb[i] = g_kb[i];
        s_vb[i] = g_vb[i];
    }
    __syncthreads();

    int warp = t >> 5, lane = t & 31;
    int p   = blockIdx.x * 8 + warp;
    int n   = p / HWSZ;
    int pix = p % HWSZ;
    int y = pix / WW, x = pix % WW;

    const float* fl = flow + (size_t)((n * HH + y) * WW + x) * 2;
    float fx = fl[0], fy = fl[1];
    int giy = (int)floorf((float)y + fy);
    int gix = (int)floorf((float)x + fx);

    int c0 = lane * 4;
    float4 qv = *(const float4*)(g_Q + (size_t)p * DIM + c0);
    const float sc = 0.25f;
    qv.x *= sc; qv.y *= sc; qv.z *= sc; qv.w *= sc;

    int nb[4];
#pragma unroll
    for (int w2 = 0; w2 < 4; ++w2) {
        int hy = giy + (w2 >> 1);
        int wx = gix + (w2 & 1);
        hy = hy < 0 ? 0 : (hy > HH - 1 ? HH - 1 : hy);
        wx = wx < 0 ? 0 : (wx > WW - 1 ? WW - 1 : wx);
        nb[w2] = n * HWSZ + hy * WW + wx;
    }
    // Batch all 8 loads (max MLP); V independent of softmax weights
    float4 kr[4], vr[4];
#pragma unroll
    for (int w2 = 0; w2 < 4; ++w2) {
        kr[w2] = *(const float4*)(g_K + (size_t)nb[w2] * DIM + c0);
        vr[w2] = *(const float4*)(g_V + (size_t)nb[w2] * DIM + c0);
    }

    float lg[4];
#pragma unroll
    for (int w2 = 0; w2 < 4; ++w2) {
        const float* kbp = s_kb + w2 * DIM + c0;
        float part = qv.x * (kr[w2].x + kbp[0]) + qv.y * (kr[w2].y + kbp[1]) +
                     qv.z * (kr[w2].z + kbp[2]) + qv.w * (kr[w2].w + kbp[3]);
        part += __shfl_xor_sync(0xffffffffu, part, 1);
        part += __shfl_xor_sync(0xffffffffu, part, 2);
        lg[w2] = part;
    }
    float mx = fmaxf(fmaxf(lg[0], lg[1]), fmaxf(lg[2], lg[3]));
    float e0 = __expf(lg[0] - mx), e1 = __expf(lg[1] - mx);
    float e2 = __expf(lg[2] - mx), e3 = __expf(lg[3] - mx);
    float inv = 1.f / (e0 + e1 + e2 + e3);
    float aw[4] = {e0 * inv, e1 * inv, e2 * inv, e3 * inv};

    float4 o = make_float4(0.f, 0.f, 0.f, 0.f);
#pragma unroll
    for (int w2 = 0; w2 < 4; ++w2) {
        const float* vbp = s_vb + w2 * DIM + c0;
        float a = aw[w2];
        o.x += a * (vr[w2].x + vbp[0]);
        o.y += a * (vr[w2].y + vbp[1]);
        o.z += a * (vr[w2].z + vbp[2]);
        o.w += a * (vr[w2].w + vbp[3]);
    }
    s_out[warp][c0 + 0] = o.x;
    s_out[warp][c0 + 1] = o.y;
    s_out[warp][c0 + 2] = o.z;
    s_out[warp][c0 + 3] = o.w;
    __syncthreads();

    int p0   = blockIdx.x * 8;
    int n0   = p0 / HWSZ;
    int pix0 = p0 % HWSZ;
    int y0 = pix0 / WW, x0 = pix0 % WW;
#pragma unroll
    for (int rep = 0; rep < 4; ++rep) {
        int d  = (t >> 3) + rep * 32;
        int px = t & 7;
        out[((size_t)(n0 * DIM + d) * HH + y0) * WW + x0 + px] = s_out[px][d];
    }
}

// ---------------------------------------------------------------------------
extern "C" void kernel_launch(void* const* d_in, const int* in_sizes, int n_in,
                              void* d_out, int out_size) {
    const float* feat_supp = (const float*)d_in[0];
    const float* feat_curr = (const float*)d_in[1];
    const float* flow      = (const float*)d_in[2];
    const float* q_w       = (const float*)d_in[3];
    const float* q_b       = (const float*)d_in[4];
    const float* k_w       = (const float*)d_in[5];
    const float* k_b       = (const float*)d_in[6];
    const float* v_w       = (const float*)d_in[7];
    const float* v_b       = (const float*)d_in[8];
    float* out = (float*)d_out;

    const int smem_kv = 3 * SKV * (int)sizeof(float);  // 153600 B
    const int smem_q  = 3 * SQ  * (int)sizeof(float);  // 104448 B
    cudaFuncSetAttribute(gemm_kv_kernel, cudaFuncAttributeMaxDynamicSharedMemorySize, smem_kv);
    cudaFuncSetAttribute(gemm_q_kernel,  cudaFuncAttributeMaxDynamicSharedMemorySize, smem_q);

    bias_kernel<<<8, 512>>>(k_w, k_b, v_w, v_b);
    gemm_kv_kernel<<<NHW / 128, 512, smem_kv>>>(feat_supp, k_w, v_w);
    gemm_q_kernel<<<NHW / 128, 512, smem_q>>>(feat_curr, flow, q_w, q_b);
    attn_kernel<<<NHW / 8, 256>>>(flow, out);
}

// round 6
// speedup vs baseline: 1.6389x; 1.0473x over previous
#include <cuda_runtime.h>
#include <cuda_fp16.h>
#include <math.h>
#include <stdint.h>

// Problem constants
#define NB   4
#define CC   128
#define HH   128
#define WW   256
#define HWSZ (HH * WW)          // 32768
#define NHW  (NB * HWSZ)        // 131072
#define DIM  128
#define NWP  4
#define APIT 136                // A smem pitch (words); %32==8 -> conflict-free frags
#define BPIT 264                // fused K|V B-panel pitch; %32==8
#define SKV  (32 * APIT + 32 * BPIT)   // words per kv stage = 12800
#define SQ   (32 * APIT + 32 * APIT)   // words per q stage  = 8704

// Device-global scratch: K/V/Q stored fp16 (halves DRAM traffic; fp32 math)
__device__ __half g_K[(size_t)NHW * DIM];
__device__ __half g_V[(size_t)NHW * DIM];
__device__ __half g_Q[(size_t)NHW * DIM];
__device__ float  g_kb[NWP * DIM];
__device__ float  g_vb[NWP * DIM];

__device__ __forceinline__ float inv_dt(int t2) {
    return exp2f(-(float)t2 * (13.287712379549449f / 32.0f));
}

__device__ __forceinline__ void cp16(uint32_t saddr, const void* g) {
    asm volatile("cp.async.cg.shared.global [%0], [%1], 16;" :: "r"(saddr), "l"(g));
}
__device__ __forceinline__ void cp_commit() {
    asm volatile("cp.async.commit_group;" ::: "memory");
}
template<int N> __device__ __forceinline__ void cp_wait() {
    asm volatile("cp.async.wait_group %0;" :: "n"(N) : "memory");
}

// tf32 mma; operands raw fp32 bit patterns (HW truncates mantissa)
__device__ __forceinline__ void mma_tf32(float d[4], const uint32_t a[4],
                                         uint32_t b0, uint32_t b1) {
    asm volatile(
        "mma.sync.aligned.m16n8k8.row.col.f32.tf32.tf32.f32 "
        "{%0,%1,%2,%3}, {%4,%5,%6,%7}, {%8,%9}, {%0,%1,%2,%3};\n"
        : "+f"(d[0]), "+f"(d[1]), "+f"(d[2]), "+f"(d[3])
        : "r"(a[0]), "r"(a[1]), "r"(a[2]), "r"(a[3]), "r"(b0), "r"(b1));
}

// ---------------------------------------------------------------------------
// Kernel 0: window position-bias projections (8 CTAs, shfl split-K)
// ---------------------------------------------------------------------------
__global__ void bias_kernel(const float* __restrict__ kw, const float* __restrict__ kb,
                            const float* __restrict__ vw, const float* __restrict__ vb) {
    __shared__ float pb[DIM];
    int t = threadIdx.x;
    int w      = blockIdx.x & 3;
    int matrix = blockIdx.x >> 2;
    if (t < DIM) {
        int oy = w >> 1, ox = w & 1;
        float coord = (t < 64) ? (float)oy : (float)ox;
        int ii = t & 63;
        int t2 = ii >> 1;
        float arg = coord * (6.283185307179586f / 1.000001f) * inv_dt(t2);
        float s, c;
        sincosf(arg, &s, &c);
        pb[t] = (ii & 1) ? c : s;
    }
    __syncthreads();

    const float* W  = matrix ? vw : kw;
    const float* Bb = matrix ? vb : kb;
    float* dst      = matrix ? g_vb : g_kb;

    int d = t >> 2, q = t & 3;
    float acc = 0.f;
    int cbase = q * 32;
#pragma unroll 8
    for (int c = 0; c < 32; ++c)
        acc += pb[cbase + c] * W[(cbase + c) * DIM + d];
    acc += __shfl_xor_sync(0xffffffffu, acc, 1);
    acc += __shfl_xor_sync(0xffffffffu, acc, 2);
    if (q == 0)
        dst[w * DIM + d] = acc + Bb[d];
}

// ---------------------------------------------------------------------------
// Kernel 1: fused g_K / g_V GEMM, 3-stage cp.async pipeline over BK=32 chunks.
// ---------------------------------------------------------------------------
struct KVFill {
    uint32_t sm_u;
    const float *feat, *kw, *vw;
    int n, pix0, t;
    __device__ __forceinline__ void operator()(int chunk, int stg) const {
        uint32_t As_u = sm_u + (uint32_t)(stg * SKV) * 4u;
        uint32_t Bs_u = As_u + 32 * APIT * 4;
        int kb = chunk * 32;
#pragma unroll
        for (int j = 0; j < 2; ++j) {
            int li = j * 512 + t;
            int r = li >> 5, m4 = li & 31;
            cp16(As_u + (r * APIT + m4 * 4) * 4,
                 feat + (size_t)(n * CC + kb + r) * HWSZ + pix0 + m4 * 4);
        }
#pragma unroll
        for (int j = 0; j < 4; ++j) {
            int li = j * 512 + t;
            int r = li >> 6, d4 = li & 63;
            const float* src = (d4 < 32) ? (kw + (kb + r) * DIM + d4 * 4)
                                         : (vw + (kb + r) * DIM + (d4 - 32) * 4);
            int col = (d4 < 32) ? (d4 * 4) : (128 + (d4 - 32) * 4);
            cp16(Bs_u + (r * BPIT + col) * 4, src);
        }
    }
};

__device__ __forceinline__ void mma_chunk_kv(const float* __restrict__ As,
                                             const float* __restrict__ Bs,
                                             float acc[2][8][4],
                                             int m0w, int n0w, int q, int g) {
#pragma unroll
    for (int ks = 0; ks < 4; ++ks) {
        int k0 = ks * 8;
        uint32_t a[2][4];
#pragma unroll
        for (int mi = 0; mi < 2; ++mi) {
            int m = m0w + mi * 16 + g;
            a[mi][0] = __float_as_uint(As[(k0 + q) * APIT + m]);
            a[mi][1] = __float_as_uint(As[(k0 + q) * APIT + m + 8]);
            a[mi][2] = __float_as_uint(As[(k0 + q + 4) * APIT + m]);
            a[mi][3] = __float_as_uint(As[(k0 + q + 4) * APIT + m + 8]);
        }
#pragma unroll
        for (int nj = 0; nj < 8; ++nj) {
            int nn = n0w + nj * 8 + g;
            uint32_t b0 = __float_as_uint(Bs[(k0 + q) * BPIT + nn]);
            uint32_t b1 = __float_as_uint(Bs[(k0 + q + 4) * BPIT + nn]);
#pragma unroll
            for (int mi = 0; mi < 2; ++mi)
                mma_tf32(acc[mi][nj], a[mi], b0, b1);
        }
    }
}

__global__ __launch_bounds__(512, 1)
void gemm_kv_kernel(const float* __restrict__ feat,
                    const float* __restrict__ kw,
                    const float* __restrict__ vw) {
    extern __shared__ float sm[];
    uint32_t sm_u = (uint32_t)__cvta_generic_to_shared(sm);
    int t  = threadIdx.x;
    int m0 = blockIdx.x * 128;
    int n    = m0 / HWSZ;
    int pix0 = m0 % HWSZ;

    KVFill fill{sm_u, feat, kw, vw, n, pix0, t};

    fill(0, 0); cp_commit();
    fill(1, 1); cp_commit();
    fill(2, 2); cp_commit();

    int w = t >> 5, lane = t & 31;
    int m0w = (w & 3) * 32, n0w = (w >> 2) * 64;
    int q = lane & 3, g = lane >> 2;

    float acc[2][8][4];
#pragma unroll
    for (int mi = 0; mi < 2; ++mi)
#pragma unroll
        for (int nj = 0; nj < 8; ++nj)
#pragma unroll
            for (int e = 0; e < 4; ++e) acc[mi][nj][e] = 0.f;

    float* st0 = sm;
    float* st1 = sm + SKV;
    float* st2 = sm + 2 * SKV;

    cp_wait<2>(); __syncthreads();
    mma_chunk_kv(st0, st0 + 32 * APIT, acc, m0w, n0w, q, g);
    __syncthreads();
    fill(3, 0); cp_commit();
    cp_wait<2>(); __syncthreads();
    mma_chunk_kv(st1, st1 + 32 * APIT, acc, m0w, n0w, q, g);
    cp_wait<1>(); __syncthreads();
    mma_chunk_kv(st2, st2 + 32 * APIT, acc, m0w, n0w, q, g);
    cp_wait<0>(); __syncthreads();
    mma_chunk_kv(st0, st0 + 32 * APIT, acc, m0w, n0w, q, g);

    // Epilogue: cols <128 -> g_K, else g_V (fp16 stores)
#pragma unroll
    for (int mi = 0; mi < 2; ++mi) {
#pragma unroll
        for (int nj = 0; nj < 8; ++nj) {
            int r0 = m0 + m0w + mi * 16 + g;
            int col = n0w + nj * 8 + q * 2;
            __half* dst = (col < 128) ? (g_K + (size_t)r0 * DIM + col)
                                      : (g_V + (size_t)r0 * DIM + (col - 128));
            *(__half2*)dst = __floats2half2_rn(acc[mi][nj][0], acc[mi][nj][1]);
            *(__half2*)(dst + (size_t)8 * DIM) =
                __floats2half2_rn(acc[mi][nj][2], acc[mi][nj][3]);
        }
    }
}

// ---------------------------------------------------------------------------
// Kernel 2: g_Q = ((feat_curr + PE(frac(flow))) @ q_w + q_b) * 0.25, pipelined.
// ---------------------------------------------------------------------------
struct QFill {
    uint32_t sm_u;
    const float *feat, *qw;
    int n, pix0, t;
    __device__ __forceinline__ void operator()(int chunk, int stg) const {
        uint32_t As_u = sm_u + (uint32_t)(stg * SQ) * 4u;
        uint32_t Bs_u = As_u + 32 * APIT * 4;
        int kb = chunk * 32;
#pragma unroll
        for (int j = 0; j < 2; ++j) {
            int li = j * 512 + t;
            int r = li >> 5, m4 = li & 31;
            cp16(As_u + (r * APIT + m4 * 4) * 4,
                 feat + (size_t)(n * CC + kb + r) * HWSZ + pix0 + m4 * 4);
        }
#pragma unroll
        for (int j = 0; j < 2; ++j) {
            int li = j * 512 + t;
            int r = li >> 5, d4 = li & 31;
            cp16(Bs_u + (r * APIT + d4 * 4) * 4, qw + (kb + r) * DIM + d4 * 4);
        }
    }
};

__device__ __forceinline__ void pe_chunk(float* __restrict__ As, int kb,
                                         const float* __restrict__ s_base,
                                         const float* __restrict__ s_idt, int t) {
#pragma unroll
    for (int j = 0; j < 4; ++j) {
        int li = j * 512 + t;
        int pi = li >> 7, m = li & 127;
        int c0 = kb + pi * 2;
        int half = (c0 >> 6) & 1;
        int t2 = (c0 & 63) >> 1;
        float arg = s_base[half * 128 + m] * s_idt[t2];
        float s, c;
        sincosf(arg, &s, &c);
        As[(pi * 2) * APIT + m]     += s;
        As[(pi * 2 + 1) * APIT + m] += c;
    }
}

__device__ __forceinline__ void mma_chunk_q(const float* __restrict__ As,
                                            const float* __restrict__ Bs,
                                            float acc[2][4][4],
                                            int m0w, int n0w, int q, int g) {
#pragma unroll
    for (int ks = 0; ks < 4; ++ks) {
        int k0 = ks * 8;
        uint32_t a[2][4];
#pragma unroll
        for (int mi = 0; mi < 2; ++mi) {
            int m = m0w + mi * 16 + g;
            a[mi][0] = __float_as_uint(As[(k0 + q) * APIT + m]);
            a[mi][1] = __float_as_uint(As[(k0 + q) * APIT + m + 8]);
            a[mi][2] = __float_as_uint(As[(k0 + q + 4) * APIT + m]);
            a[mi][3] = __float_as_uint(As[(k0 + q + 4) * APIT + m + 8]);
        }
#pragma unroll
        for (int nj = 0; nj < 4; ++nj) {
            int nn = n0w + nj * 8 + g;
            uint32_t b0 = __float_as_uint(Bs[(k0 + q) * APIT + nn]);
            uint32_t b1 = __float_as_uint(Bs[(k0 + q + 4) * APIT + nn]);
#pragma unroll
            for (int mi = 0; mi < 2; ++mi)
                mma_tf32(acc[mi][nj], a[mi], b0, b1);
        }
    }
}

__global__ __launch_bounds__(512, 1)
void gemm_q_kernel(const float* __restrict__ feat,
                   const float* __restrict__ flow,
                   const float* __restrict__ qw,
                   const float* __restrict__ qb) {
    extern __shared__ float sm[];
    __shared__ float s_base[2 * 128];
    __shared__ float s_idt[32];
    uint32_t sm_u = (uint32_t)__cvta_generic_to_shared(sm);
    int t  = threadIdx.x;
    int m0 = blockIdx.x * 128;
    int n    = m0 / HWSZ;
    int pix0 = m0 % HWSZ;

    QFill fill{sm_u, feat, qw, n, pix0, t};
    fill(0, 0); cp_commit();
    fill(1, 1); cp_commit();
    fill(2, 2); cp_commit();

    if (t < 32) s_idt[t] = inv_dt(t);
    if (t < 256) {
        int m    = t >> 1;
        int half = t & 1;
        int pix  = pix0 + m;
        int yy = pix / WW, xx = pix % WW;
        const float* fl = flow + (size_t)((n * HH + yy) * WW + xx) * 2;
        float fx = fl[0], fy = fl[1];
        float full = half ? ((float)xx + fx) : ((float)yy + fy);
        float dec  = full - floorf(full);
        s_base[half * 128 + m] = dec * (6.283185307179586f / 2.000001f);
    }

    int w = t >> 5, lane = t & 31;
    int m0w = (w & 3) * 32, n0w = (w >> 2) * 32;
    int q = lane & 3, g = lane >> 2;

    float acc[2][4][4];
#pragma unroll
    for (int mi = 0; mi < 2; ++mi)
#pragma unroll
        for (int nj = 0; nj < 4; ++nj)
#pragma unroll
            for (int e = 0; e < 4; ++e) acc[mi][nj][e] = 0.f;

    float* st0 = sm;
    float* st1 = sm + SQ;
    float* st2 = sm + 2 * SQ;

    cp_wait<2>(); __syncthreads();
    pe_chunk(st0, 0, s_base, s_idt, t);
    __syncthreads();
    mma_chunk_q(st0, st0 + 32 * APIT, acc, m0w, n0w, q, g);
    __syncthreads();
    fill(3, 0); cp_commit();
    cp_wait<2>(); __syncthreads();
    pe_chunk(st1, 32, s_base, s_idt, t);
    __syncthreads();
    mma_chunk_q(st1, st1 + 32 * APIT, acc, m0w, n0w, q, g);
    cp_wait<1>(); __syncthreads();
    pe_chunk(st2, 64, s_base, s_idt, t);
    __syncthreads();
    mma_chunk_q(st2, st2 + 32 * APIT, acc, m0w, n0w, q, g);
    cp_wait<0>(); __syncthreads();
    pe_chunk(st0, 96, s_base, s_idt, t);
    __syncthreads();
    mma_chunk_q(st0, st0 + 32 * APIT, acc, m0w, n0w, q, g);

    const float sc = 0.25f;   // head scale folded into stored Q
#pragma unroll
    for (int mi = 0; mi < 2; ++mi) {
#pragma unroll
        for (int nj = 0; nj < 4; ++nj) {
            int r0 = m0 + m0w + mi * 16 + g;
            int cb = n0w + nj * 8 + q * 2;
            float b0 = qb[cb], b1 = qb[cb + 1];
            *(__half2*)(g_Q + (size_t)r0 * DIM + cb) =
                __floats2half2_rn((acc[mi][nj][0] + b0) * sc, (acc[mi][nj][1] + b1) * sc);
            *(__half2*)(g_Q + (size_t)(r0 + 8) * DIM + cb) =
                __floats2half2_rn((acc[mi][nj][2] + b0) * sc, (acc[mi][nj][3] + b1) * sc);
        }
    }
}

// ---------------------------------------------------------------------------
// Kernel 3: per-pixel attention; fp16 gathers, fp32 math
// ---------------------------------------------------------------------------
__global__ void attn_kernel(const float* __restrict__ flow, float* __restrict__ out) {
    __shared__ float s_out[8][132];
    __shared__ float s_kb[NWP * DIM];
    __shared__ float s_vb[NWP * DIM];
    int t = threadIdx.x;
    for (int i = t; i < NWP * DIM; i += 256) {
        s_kb[i] = g_kb[i];
        s_vb[i] = g_vb[i];
    }
    __syncthreads();

    int warp = t >> 5, lane = t & 31;
    int p   = blockIdx.x * 8 + warp;
    int n   = p / HWSZ;
    int pix = p % HWSZ;
    int y = pix / WW, x = pix % WW;

    const float* fl = flow + (size_t)((n * HH + y) * WW + x) * 2;
    float fx = fl[0], fy = fl[1];
    int giy = (int)floorf((float)y + fy);
    int gix = (int)floorf((float)x + fx);

    int c0 = lane * 4;
    uint2 qraw = *(const uint2*)(g_Q + (size_t)p * DIM + c0);
    float2 qa = __half22float2(*(__half2*)&qraw.x);
    float2 qc = __half22float2(*(__half2*)&qraw.y);

    int nb[4];
#pragma unroll
    for (int w2 = 0; w2 < 4; ++w2) {
        int hy = giy + (w2 >> 1);
        int wx = gix + (w2 & 1);
        hy = hy < 0 ? 0 : (hy > HH - 1 ? HH - 1 : hy);
        wx = wx < 0 ? 0 : (wx > WW - 1 ? WW - 1 : wx);
        nb[w2] = n * HWSZ + hy * WW + wx;
    }
    // Batch all 8 gathers (max MLP)
    uint2 kraw[4], vraw[4];
#pragma unroll
    for (int w2 = 0; w2 < 4; ++w2) {
        kraw[w2] = *(const uint2*)(g_K + (size_t)nb[w2] * DIM + c0);
        vraw[w2] = *(const uint2*)(g_V + (size_t)nb[w2] * DIM + c0);
    }

    float lg[4];
#pragma unroll
    for (int w2 = 0; w2 < 4; ++w2) {
        float2 k01 = __half22float2(*(__half2*)&kraw[w2].x);
        float2 k23 = __half22float2(*(__half2*)&kraw[w2].y);
        const float* kbp = s_kb + w2 * DIM + c0;
        float part = qa.x * (k01.x + kbp[0]) + qa.y * (k01.y + kbp[1]) +
                     qc.x * (k23.x + kbp[2]) + qc.y * (k23.y + kbp[3]);
        part += __shfl_xor_sync(0xffffffffu, part, 1);
        part += __shfl_xor_sync(0xffffffffu, part, 2);
        lg[w2] = part;
    }
    float mx = fmaxf(fmaxf(lg[0], lg[1]), fmaxf(lg[2], lg[3]));
    float e0 = __expf(lg[0] - mx), e1 = __expf(lg[1] - mx);
    float e2 = __expf(lg[2] - mx), e3 = __expf(lg[3] - mx);
    float inv = 1.f / (e0 + e1 + e2 + e3);
    float aw[4] = {e0 * inv, e1 * inv, e2 * inv, e3 * inv};

    float4 o = make_float4(0.f, 0.f, 0.f, 0.f);
#pragma unroll
    for (int w2 = 0; w2 < 4; ++w2) {
        float2 v01 = __half22float2(*(__half2*)&vraw[w2].x);
        float2 v23 = __half22float2(*(__half2*)&vraw[w2].y);
        const float* vbp = s_vb + w2 * DIM + c0;
        float a = aw[w2];
        o.x += a * (v01.x + vbp[0]);
        o.y += a * (v01.y + vbp[1]);
        o.z += a * (v23.x + vbp[2]);
        o.w += a * (v23.y + vbp[3]);
    }
    s_out[warp][c0 + 0] = o.x;
    s_out[warp][c0 + 1] = o.y;
    s_out[warp][c0 + 2] = o.z;
    s_out[warp][c0 + 3] = o.w;
    __syncthreads();

    int p0   = blockIdx.x * 8;
    int n0   = p0 / HWSZ;
    int pix0 = p0 % HWSZ;
    int y0 = pix0 / WW, x0 = pix0 % WW;
#pragma unroll
    for (int rep = 0; rep < 4; ++rep) {
        int d  = (t >> 3) + rep * 32;
        int px = t & 7;
        out[((size_t)(n0 * DIM + d) * HH + y0) * WW + x0 + px] = s_out[px][d];
    }
}

// ---------------------------------------------------------------------------
extern "C" void kernel_launch(void* const* d_in, const int* in_sizes, int n_in,
                              void* d_out, int out_size) {
    const float* feat_supp = (const float*)d_in[0];
    const float* feat_curr = (const float*)d_in[1];
    const float* flow      = (const float*)d_in[2];
    const float* q_w       = (const float*)d_in[3];
    const float* q_b       = (const float*)d_in[4];
    const float* k_w       = (const float*)d_in[5];
    const float* k_b       = (const float*)d_in[6];
    const float* v_w       = (const float*)d_in[7];
    const float* v_b       = (const float*)d_in[8];
    float* out = (float*)d_out;

    const int smem_kv = 3 * SKV * (int)sizeof(float);  // 153600 B
    const int smem_q  = 3 * SQ  * (int)sizeof(float);  // 104448 B
    cudaFuncSetAttribute(gemm_kv_kernel, cudaFuncAttributeMaxDynamicSharedMemorySize, smem_kv);
    cudaFuncSetAttribute(gemm_q_kernel,  cudaFuncAttributeMaxDynamicSharedMemorySize, smem_q);

    bias_kernel<<<8, 512>>>(k_w, k_b, v_w, v_b);
    gemm_kv_kernel<<<NHW / 128, 512, smem_kv>>>(feat_supp, k_w, v_w);
    gemm_q_kernel<<<NHW / 128, 512, smem_q>>>(feat_curr, flow, q_w, q_b);
    attn_kernel<<<NHW / 8, 256>>>(flow, out);
}